// round 15
// baseline (speedup 1.0000x reference)
#include <cuda_runtime.h>
#include <cstdint>

#define BATCH 4
#define CH    64
#define NPTS  4096
#define KNN   32
#define NOUT  64
#define NCHUNK (NPTS/128)

// ---------------- device scratch (static: no allocations allowed) ----------------
__device__ float g_sq   [BATCH*NPTS];
__device__ int   g_idx  [BATCH*NPTS*KNN];
__device__ float g_Y1   [BATCH*NPTS*NOUT];
__device__ float g_Y2   [BATCH*NPTS*NOUT];
__device__ float g_hmax [BATCH*NPTS*NOUT];
__device__ float g_hmin [BATCH*NPTS*NOUT];
__device__ float g_Wt1  [CH*NOUT];
__device__ float g_Wt2  [CH*NOUT];
__device__ float g_sum  [NOUT];
__device__ float g_sumsq[NOUT];
__device__ float g_a    [NOUT];
__device__ float g_c    [NOUT];

// ---------------- packed fp32x2 helpers (Blackwell FFMA2) ----------------
__device__ __forceinline__ unsigned long long fma2(unsigned long long a,
                                                   unsigned long long b,
                                                   unsigned long long c){
    unsigned long long d;
    asm("fma.rn.f32x2 %0, %1, %2, %3;" : "=l"(d) : "l"(a), "l"(b), "l"(c));
    return d;
}
__device__ __forceinline__ float2 u2f2(unsigned long long u){
    float2 f;
    asm("mov.b64 {%0, %1}, %2;" : "=f"(f.x), "=f"(f.y) : "l"(u));
    return f;
}
__device__ __forceinline__ uint32_t smem_u32(const void* p){
    uint32_t a;
    asm("{ .reg .u64 t; cvta.to.shared.u64 t, %1; cvt.u32.u64 %0, t; }" : "=r"(a) : "l"(p));
    return a;
}
__device__ __forceinline__ void cp16(uint32_t dst, const void* src){
    asm volatile("cp.async.ca.shared.global [%0], [%1], 16;" :: "r"(dst), "l"(src));
}

// ---------------- kernel 0a: Wt1 = (W1-W2)^T, Wt2 = W2^T ----------------
__global__ void wprep_kernel(const float* __restrict__ W){
    int t = blockIdx.x*256 + threadIdx.x;
    if (t < CH*NOUT){
        int o = t & 63, c = t >> 6;
        float w1 = W[o*2*CH + c];
        float w2 = W[o*2*CH + CH + c];
        g_Wt1[c*NOUT + o] = w1 - w2;
        g_Wt2[c*NOUT + o] = w2;
    }
}

// ---------------- kernel 0b: squared norms ----------------
__global__ void sqnorm_kernel(const float* __restrict__ points){
    int t = blockIdx.x*256 + threadIdx.x;         // 0..16383
    int b = t >> 12, n = t & (NPTS-1);
    const float* P = points + b*CH*NPTS + n;
    float s = 0.f;
    #pragma unroll
    for (int c = 0; c < CH; ++c){ float v = __ldg(P + c*NPTS); s = fmaf(v, v, s); }
    g_sq[t] = s;
}

// ---------------- kernel 0c: zero BN accumulators (graph replays!) ----------------
__global__ void zero_kernel(){
    int t = threadIdx.x;
    if (t < NOUT){ g_sum[t] = 0.f; g_sumsq[t] = 0.f; }
}

// ---------------- kernel 1: fused distance GEMM + register top-32 ----------------
// grid = BATCH*64 blocks x 512 threads (16 warps), 2 blocks/SM.
// Block owns 64 queries; warp w owns queries [4w, 4w+4). Streams 4096
// candidates in chunks of 128, double-buffered via cp.async with ONE
// __syncthreads per chunk (wait -> sync -> prefetch(k+1) -> compute(k)).
// Qd holds queries DUPLICATED and pre-scaled by -2 (Qd[c][2q]=Qd[c][2q+1]);
// accumulators pair adjacent CANDIDATES, so candidate float4 loads give two
// natural u64 operand pairs and sq-init loads directly as pairs: ZERO packs
// in the inner loop (11 issues per c-step vs 14).
// score = sq_m - 2*dot accumulates directly ((-2q)*x bit-identical to
// q*(-2x)). Selection = R12 short-chain sorted-list inserts.
// smem: Qd[64][128] 32K + Cs 2x[64][128] 64K + Ss[4096] 16K = 112KB.
__global__ void __launch_bounds__(512, 2) knn_kernel(const float* __restrict__ points){
    extern __shared__ float sm[];
    float* Qd = sm;               // [64][128]  duplicated, scaled by -2
    float* Cs = Qd + 64*128;      // 2 x [64][128] (raw candidates)
    float* Ss = Cs + 2*64*128;    // [4096] candidate sq-norms
    const uint32_t csb = smem_u32(Cs);

    const int tid  = threadIdx.x;
    const int lane = tid & 31;
    const int wid  = tid >> 5;
    const int b     = blockIdx.x >> 6;
    const int qbase = (blockIdx.x & 63) * 64;
    const float* P = points + b*CH*NPTS;

    // load query tile duplicated + scaled by -2  (1024 float4 -> 2 each)
    #pragma unroll
    for (int it = 0; it < 2; ++it){
        int idx = it*512 + tid;
        int c = idx >> 4, i4 = idx & 15;
        float4 v = __ldg(reinterpret_cast<const float4*>(P + c*NPTS + qbase) + i4);
        v.x *= -2.f; v.y *= -2.f; v.z *= -2.f; v.w *= -2.f;
        float4* dst = reinterpret_cast<float4*>(Qd + c*128 + i4*8);
        dst[0] = make_float4(v.x, v.x, v.y, v.y);
        dst[1] = make_float4(v.z, v.z, v.w, v.w);
    }
    // load sq-norm cache (1024 float4 -> 2 each)
    #pragma unroll
    for (int it = 0; it < 2; ++it){
        int idx = it*512 + tid;
        reinterpret_cast<float4*>(Ss)[idx] =
            __ldg(reinterpret_cast<const float4*>(g_sq + b*NPTS) + idx);
    }

    // prologue: async-fill chunk 0 into buffer 0
    #pragma unroll
    for (int it = 0; it < 4; ++it){
        int idx = it*512 + tid;
        int c = idx >> 5, i4 = idx & 31;
        cp16(csb + (uint32_t)((c*128 + i4*4)*4), P + c*NPTS + i4*4);
    }
    asm volatile("cp.async.commit_group;");

    // per-(warp,query) sorted list: lane l holds l-th smallest
    float Lv[4]; int Li[4]; float thr[4];
    #pragma unroll
    for (int qi = 0; qi < 4; ++qi){ Lv[qi] = 3.0e38f; Li[qi] = 0; thr[qi] = 3.0e38f; }

    const int q0 = wid * 4;      // this warp's first query
    const int m0 = lane * 4;     // this lane's candidate base within chunk

    #pragma unroll 1
    for (int chunk = 0; chunk < NCHUNK; ++chunk){
        const int mbase = chunk * 128;
        const float* Cb = Cs + (chunk & 1) * (64*128);

        asm volatile("cp.async.wait_group 0;");   // my chunk-k copies landed
        __syncthreads();                          // all copies visible + prev compute done

        // issue prefetch of chunk k+1 into the other buffer (race-free post-sync)
        if (chunk + 1 < NCHUNK){
            const uint32_t dstb = csb + (uint32_t)(((chunk+1) & 1) * 64*128*4);
            const float* src = P + (chunk+1)*128;
            #pragma unroll
            for (int it = 0; it < 4; ++it){
                int idx = it*512 + tid;
                int c = idx >> 5, i4 = idx & 31;
                cp16(dstb + (uint32_t)((c*128 + i4*4)*4), src + c*NPTS + i4*4);
            }
            asm volatile("cp.async.commit_group;");
        }

        // acc init = sq of candidates, loaded directly as adjacent pairs
        ulonglong2 sqp = *reinterpret_cast<const ulonglong2*>(Ss + mbase + m0);
        unsigned long long acc[4][2];
        #pragma unroll
        for (int qi = 0; qi < 4; ++qi){ acc[qi][0] = sqp.x; acc[qi][1] = sqp.y; }

        // GEMM: 4 queries (duplicated-pair operands) x 2 candidate-pairs per lane
        #pragma unroll 4
        for (int c = 0; c < CH; ++c){
            const float* qrow = Qd + c*128 + q0*2;
            ulonglong2 qva = *reinterpret_cast<const ulonglong2*>(qrow);      // (q0,q0),(q1,q1)
            ulonglong2 qvb = *reinterpret_cast<const ulonglong2*>(qrow + 4);  // (q2,q2),(q3,q3)
            ulonglong2 cvp = *reinterpret_cast<const ulonglong2*>(Cb + c*128 + m0);
            acc[0][0] = fma2(qva.x, cvp.x, acc[0][0]);
            acc[0][1] = fma2(qva.x, cvp.y, acc[0][1]);
            acc[1][0] = fma2(qva.y, cvp.x, acc[1][0]);
            acc[1][1] = fma2(qva.y, cvp.y, acc[1][1]);
            acc[2][0] = fma2(qvb.x, cvp.x, acc[2][0]);
            acc[2][1] = fma2(qvb.x, cvp.y, acc[2][1]);
            acc[3][0] = fma2(qvb.y, cvp.x, acc[3][0]);
            acc[3][1] = fma2(qvb.y, cvp.y, acc[3][1]);
        }

        // unpack scores: sc[qi][j] = score of candidate m0+j (ascending m)
        float sc[4][4];
        #pragma unroll
        for (int qi = 0; qi < 4; ++qi){
            float2 d0 = u2f2(acc[qi][0]), d1 = u2f2(acc[qi][1]);
            sc[qi][0] = d0.x; sc[qi][1] = d0.y; sc[qi][2] = d1.x; sc[qi][3] = d1.y;
        }

        // selection with per-query min-prefilter; short insert chains
        #pragma unroll
        for (int qi = 0; qi < 4; ++qi){
            float mn = fminf(fminf(sc[qi][0], sc[qi][1]), fminf(sc[qi][2], sc[qi][3]));
            if (!__any_sync(0xffffffffu, mn < thr[qi])) continue;
            #pragma unroll
            for (int j = 0; j < 4; ++j){
                float sj = sc[qi][j];
                unsigned mask = __ballot_sync(0xffffffffu, sj < thr[qi]);
                while (mask){
                    int src = __ffs(mask) - 1;
                    mask &= mask - 1;
                    float v = __shfl_sync(0xffffffffu, sj, src);
                    int gi = mbase + src*4 + j;
                    int pos = __popc(__ballot_sync(0xffffffffu, Lv[qi] <= v));
                    float upv = __shfl_up_sync(0xffffffffu, Lv[qi], 1);
                    int   upi = __shfl_up_sync(0xffffffffu, Li[qi], 1);
                    if (lane == pos){ Lv[qi] = v; Li[qi] = gi; }
                    else if (lane > pos){ Lv[qi] = upv; Li[qi] = upi; }
                }
                thr[qi] = __shfl_sync(0xffffffffu, Lv[qi], 31);  // once per j
            }
        }
        // no trailing sync: next iteration's wait+sync gates everything
    }

    // write indices: lane l holds l-th nearest of each owned query
    #pragma unroll
    for (int qi = 0; qi < 4; ++qi)
        g_idx[(b*NPTS + qbase + q0 + qi)*KNN + lane] = Li[qi];
}

// ---------------- kernel 2: Y1 = X*(W1-W2)^T, Y2 = X*W2^T ----------------
__global__ void __launch_bounds__(256, 1) ygemm_kernel(const float* __restrict__ points){
    extern __shared__ float smf[];
    float* Xs  = smf;           // [64][128]
    float* W1s = Xs + 64*128;   // [64][64]
    float* W2s = W1s + 64*64;   // [64][64]

    const int tid = threadIdx.x;
    const int b = blockIdx.x >> 5;
    const int nbase = (blockIdx.x & 31) * 128;
    const float* P = points + b*CH*NPTS;

    #pragma unroll
    for (int it = 0; it < 8; ++it){
        int idx = it*256 + tid;
        int c = idx >> 5, i4 = idx & 31;
        reinterpret_cast<float4*>(Xs + c*128)[i4] =
            __ldg(reinterpret_cast<const float4*>(P + c*NPTS + nbase) + i4);
    }
    #pragma unroll
    for (int it = 0; it < 4; ++it){
        int idx = it*256 + tid;
        reinterpret_cast<float4*>(W1s)[idx] = __ldg(reinterpret_cast<const float4*>(g_Wt1) + idx);
        reinterpret_cast<float4*>(W2s)[idx] = __ldg(reinterpret_cast<const float4*>(g_Wt2) + idx);
    }
    __syncthreads();

    const int n0 = (tid & 31) * 4;
    const int o0 = (tid >> 5) * 8;
    float acc1[4][8], acc2[4][8];
    #pragma unroll
    for (int j = 0; j < 4; ++j)
        #pragma unroll
        for (int r = 0; r < 8; ++r){ acc1[j][r] = 0.f; acc2[j][r] = 0.f; }

    #pragma unroll 8
    for (int c = 0; c < CH; ++c){
        float4 a   = *reinterpret_cast<const float4*>(Xs  + c*128 + n0);
        float4 w10 = *reinterpret_cast<const float4*>(W1s + c*64 + o0);
        float4 w11 = *reinterpret_cast<const float4*>(W1s + c*64 + o0 + 4);
        float4 w20 = *reinterpret_cast<const float4*>(W2s + c*64 + o0);
        float4 w21 = *reinterpret_cast<const float4*>(W2s + c*64 + o0 + 4);
        float af[4]  = {a.x, a.y, a.z, a.w};
        float w1f[8] = {w10.x,w10.y,w10.z,w10.w,w11.x,w11.y,w11.z,w11.w};
        float w2f[8] = {w20.x,w20.y,w20.z,w20.w,w21.x,w21.y,w21.z,w21.w};
        #pragma unroll
        for (int j = 0; j < 4; ++j)
            #pragma unroll
            for (int r = 0; r < 8; ++r){
                acc1[j][r] = fmaf(af[j], w1f[r], acc1[j][r]);
                acc2[j][r] = fmaf(af[j], w2f[r], acc2[j][r]);
            }
    }

    #pragma unroll
    for (int j = 0; j < 4; ++j){
        int row = (b*NPTS + nbase + n0 + j)*NOUT + o0;
        *reinterpret_cast<float4*>(g_Y1 + row)     = make_float4(acc1[j][0],acc1[j][1],acc1[j][2],acc1[j][3]);
        *reinterpret_cast<float4*>(g_Y1 + row + 4) = make_float4(acc1[j][4],acc1[j][5],acc1[j][6],acc1[j][7]);
        *reinterpret_cast<float4*>(g_Y2 + row)     = make_float4(acc2[j][0],acc2[j][1],acc2[j][2],acc2[j][3]);
        *reinterpret_cast<float4*>(g_Y2 + row + 4) = make_float4(acc2[j][4],acc2[j][5],acc2[j][6],acc2[j][7]);
    }
}

// ---------------- kernel 3: gather neighbors, h stats, per-(n,o) max/min over k ----------------
__global__ void __launch_bounds__(256, 1) gather_kernel(){
    __shared__ float ssum[NOUT], ssum2[NOUT];
    const int tid = threadIdx.x;
    if (tid < NOUT){ ssum[tid] = 0.f; ssum2[tid] = 0.f; }
    __syncthreads();

    const int b = blockIdx.x >> 6;
    const int nbase = (blockIdx.x & 63) * 64;
    const int lane = tid & 31, wid = tid >> 5;
    const int half = lane >> 4;
    const int c4 = lane & 15;

    const float4* Y1f = reinterpret_cast<const float4*>(g_Y1);
    const float4* Y2f = reinterpret_cast<const float4*>(g_Y2);
    float4* hmaxf = reinterpret_cast<float4*>(g_hmax);
    float4* hminf = reinterpret_cast<float4*>(g_hmin);

    float a0=0.f, a1=0.f, a2=0.f, a3=0.f;
    float b0=0.f, b1=0.f, b2=0.f, b3=0.f;

    #pragma unroll 1
    for (int it = 0; it < 4; ++it){
        int np  = nbase + it*16 + wid*2;
        int bnp = b*NPTS + np;
        int ia = g_idx[ bnp   *KNN + lane];
        int ib = g_idx[(bnp+1)*KNN + lane];
        int bn = bnp + half;
        float4 y1 = __ldg(Y1f + bn*16 + c4);
        float4 mx = make_float4(-3.0e38f,-3.0e38f,-3.0e38f,-3.0e38f);
        float4 mn = make_float4( 3.0e38f, 3.0e38f, 3.0e38f, 3.0e38f);
        #pragma unroll
        for (int k = 0; k < KNN; ++k){
            int ma = __shfl_sync(0xffffffffu, ia, k);
            int mb = __shfl_sync(0xffffffffu, ib, k);
            int m  = half ? mb : ma;
            float4 y2 = __ldg(Y2f + (b*NPTS + m)*16 + c4);
            float h0 = y1.x + y2.x, h1 = y1.y + y2.y, h2 = y1.z + y2.z, h3 = y1.w + y2.w;
            a0 += h0; a1 += h1; a2 += h2; a3 += h3;
            b0 = fmaf(h0,h0,b0); b1 = fmaf(h1,h1,b1); b2 = fmaf(h2,h2,b2); b3 = fmaf(h3,h3,b3);
            mx.x = fmaxf(mx.x,h0); mx.y = fmaxf(mx.y,h1); mx.z = fmaxf(mx.z,h2); mx.w = fmaxf(mx.w,h3);
            mn.x = fminf(mn.x,h0); mn.y = fminf(mn.y,h1); mn.z = fminf(mn.z,h2); mn.w = fminf(mn.w,h3);
        }
        hmaxf[bn*16 + c4] = mx;
        hminf[bn*16 + c4] = mn;
    }

    atomicAdd(&ssum [c4*4+0], a0); atomicAdd(&ssum [c4*4+1], a1);
    atomicAdd(&ssum [c4*4+2], a2); atomicAdd(&ssum [c4*4+3], a3);
    atomicAdd(&ssum2[c4*4+0], b0); atomicAdd(&ssum2[c4*4+1], b1);
    atomicAdd(&ssum2[c4*4+2], b2); atomicAdd(&ssum2[c4*4+3], b3);
    __syncthreads();
    if (tid < NOUT){
        atomicAdd(&g_sum[tid],   ssum[tid]);
        atomicAdd(&g_sumsq[tid], ssum2[tid]);
    }
}

// ---------------- kernel 4: BN scale/shift ----------------
__global__ void finalize_kernel(const float* __restrict__ gamma,
                                const float* __restrict__ beta){
    int o = threadIdx.x;
    if (o < NOUT){
        const float inv = 1.f / (float)(BATCH*NPTS*KNN);
        float mean = g_sum[o] * inv;
        float var  = g_sumsq[o] * inv - mean*mean;
        float a = gamma[o] * rsqrtf(var + 1e-5f);
        g_a[o] = a;
        g_c[o] = beta[o] - a*mean;
    }
}

// ---------------- kernel 5: affine + relu + transpose to (B,O,N) ----------------
__global__ void __launch_bounds__(256, 1) output_kernel(float* __restrict__ out){
    __shared__ float smx[64][65];
    __shared__ float smn[64][65];
    const int tid = threadIdx.x;
    const int b = blockIdx.x >> 6;
    const int nbase = (blockIdx.x & 63) * 64;
    const float4* hmaxf = reinterpret_cast<const float4*>(g_hmax);
    const float4* hminf = reinterpret_cast<const float4*>(g_hmin);

    #pragma unroll
    for (int it = 0; it < 4; ++it){
        int idx = it*256 + tid;
        int r = idx >> 4, cc = idx & 15;
        float4 v = __ldg(hmaxf + (b*NPTS + nbase + r)*16 + cc);
        smx[r][cc*4+0] = v.x; smx[r][cc*4+1] = v.y; smx[r][cc*4+2] = v.z; smx[r][cc*4+3] = v.w;
        float4 w = __ldg(hminf + (b*NPTS + nbase + r)*16 + cc);
        smn[r][cc*4+0] = w.x; smn[r][cc*4+1] = w.y; smn[r][cc*4+2] = w.z; smn[r][cc*4+3] = w.w;
    }
    __syncthreads();

    #pragma unroll
    for (int it = 0; it < 16; ++it){
        int o  = it*4 + (tid >> 6);
        int nn = tid & 63;
        float a = g_a[o], c = g_c[o];
        float h = (a >= 0.f) ? smx[nn][o] : smn[nn][o];
        out[b*NOUT*NPTS + o*NPTS + nbase + nn] = fmaxf(fmaf(a, h, c), 0.f);
    }
}

// ---------------- launch ----------------
extern "C" void kernel_launch(void* const* d_in, const int* in_sizes, int n_in,
                              void* d_out, int out_size){
    const float* points = (const float*)d_in[0];   // (B, C, N)
    const float* W      = (const float*)d_in[1];   // (O, 2C)
    const float* gamma  = (const float*)d_in[2];   // (O,)
    const float* beta   = (const float*)d_in[3];   // (O,)
    float* out = (float*)d_out;                    // (B, O, N)

    const int KNN_SMEM = (64*128 + 2*64*128 + 4096) * 4;   // 114688 B
    cudaFuncSetAttribute((const void*)knn_kernel,
                         cudaFuncAttributeMaxDynamicSharedMemorySize, KNN_SMEM);
    cudaFuncSetAttribute((const void*)ygemm_kernel,
                         cudaFuncAttributeMaxDynamicSharedMemorySize, 64*1024);

    wprep_kernel   <<<16, 256>>>(W);
    sqnorm_kernel  <<<64, 256>>>(points);
    zero_kernel    <<<1, 64>>>();
    knn_kernel     <<<BATCH*(NPTS/64), 512, KNN_SMEM>>>(points);
    ygemm_kernel   <<<BATCH*(NPTS/128), 256, 64*1024>>>(points);
    gather_kernel  <<<BATCH*(NPTS/64), 256>>>();
    finalize_kernel<<<1, 64>>>(gamma, beta);
    output_kernel  <<<BATCH*(NPTS/64), 256>>>(out);
}

// round 16
// speedup vs baseline: 1.0015x; 1.0015x over previous
#include <cuda_runtime.h>
#include <cstdint>

#define BATCH 4
#define CH    64
#define NPTS  4096
#define KNN   32
#define NOUT  64
#define NCHUNK (NPTS/128)

// ---------------- device scratch (static: no allocations allowed) ----------------
__device__ float g_sq   [BATCH*NPTS];
__device__ int   g_idx  [BATCH*NPTS*KNN];
__device__ float g_Y1   [BATCH*NPTS*NOUT];
__device__ float g_Y2   [BATCH*NPTS*NOUT];
__device__ float g_hmax [BATCH*NPTS*NOUT];
__device__ float g_hmin [BATCH*NPTS*NOUT];
__device__ float g_Wt1  [CH*NOUT];
__device__ float g_Wt2  [CH*NOUT];
__device__ float g_sum  [NOUT];
__device__ float g_sumsq[NOUT];
__device__ float g_a    [NOUT];
__device__ float g_c    [NOUT];

// ---------------- packed fp32x2 helpers (Blackwell FFMA2) ----------------
__device__ __forceinline__ unsigned long long fma2(unsigned long long a,
                                                   unsigned long long b,
                                                   unsigned long long c){
    unsigned long long d;
    asm("fma.rn.f32x2 %0, %1, %2, %3;" : "=l"(d) : "l"(a), "l"(b), "l"(c));
    return d;
}
__device__ __forceinline__ float2 u2f2(unsigned long long u){
    float2 f;
    asm("mov.b64 {%0, %1}, %2;" : "=f"(f.x), "=f"(f.y) : "l"(u));
    return f;
}
__device__ __forceinline__ uint32_t smem_u32(const void* p){
    uint32_t a;
    asm("{ .reg .u64 t; cvta.to.shared.u64 t, %1; cvt.u32.u64 %0, t; }" : "=r"(a) : "l"(p));
    return a;
}
__device__ __forceinline__ void cp16(uint32_t dst, const void* src){
    asm volatile("cp.async.ca.shared.global [%0], [%1], 16;" :: "r"(dst), "l"(src));
}

// ---------------- kernel 0a: Wt1 = (W1-W2)^T, Wt2 = W2^T ----------------
__global__ void wprep_kernel(const float* __restrict__ W){
    int t = blockIdx.x*256 + threadIdx.x;
    if (t < CH*NOUT){
        int o = t & 63, c = t >> 6;
        float w1 = W[o*2*CH + c];
        float w2 = W[o*2*CH + CH + c];
        g_Wt1[c*NOUT + o] = w1 - w2;
        g_Wt2[c*NOUT + o] = w2;
    }
}

// ---------------- kernel 0b: squared norms ----------------
__global__ void sqnorm_kernel(const float* __restrict__ points){
    int t = blockIdx.x*256 + threadIdx.x;         // 0..16383
    int b = t >> 12, n = t & (NPTS-1);
    const float* P = points + b*CH*NPTS + n;
    float s = 0.f;
    #pragma unroll
    for (int c = 0; c < CH; ++c){ float v = __ldg(P + c*NPTS); s = fmaf(v, v, s); }
    g_sq[t] = s;
}

// ---------------- kernel 0c: zero BN accumulators (graph replays!) ----------------
__global__ void zero_kernel(){
    int t = threadIdx.x;
    if (t < NOUT){ g_sum[t] = 0.f; g_sumsq[t] = 0.f; }
}

// ---------------- kernel 1: fused distance GEMM + register top-32 ----------------
// grid = BATCH*64 blocks x 512 threads (16 warps), 2 blocks/SM.
// Block owns 64 queries; warp w owns queries [4w, 4w+4). Streams 4096
// candidates in chunks of 128, double-buffered via cp.async with ONE
// __syncthreads per chunk (wait -> sync -> prefetch(k+1) -> compute(k)).
// Qd holds queries DUPLICATED and pre-scaled by -2 (Qd[c][2q]=Qd[c][2q+1]);
// accumulators pair adjacent CANDIDATES, so candidate float4 loads give two
// natural u64 operand pairs and sq-init loads directly as pairs: ZERO packs
// in the inner loop (11 issues per c-step vs 14).
// score = sq_m - 2*dot accumulates directly ((-2q)*x bit-identical to
// q*(-2x)). Selection = R12 short-chain sorted-list inserts.
// smem: Qd[64][128] 32K + Cs 2x[64][128] 64K + Ss[4096] 16K = 112KB.
__global__ void __launch_bounds__(512, 2) knn_kernel(const float* __restrict__ points){
    extern __shared__ float sm[];
    float* Qd = sm;               // [64][128]  duplicated, scaled by -2
    float* Cs = Qd + 64*128;      // 2 x [64][128] (raw candidates)
    float* Ss = Cs + 2*64*128;    // [4096] candidate sq-norms
    const uint32_t csb = smem_u32(Cs);

    const int tid  = threadIdx.x;
    const int lane = tid & 31;
    const int wid  = tid >> 5;
    const int b     = blockIdx.x >> 6;
    const int qbase = (blockIdx.x & 63) * 64;
    const float* P = points + b*CH*NPTS;

    // load query tile duplicated + scaled by -2  (1024 float4 -> 2 each)
    #pragma unroll
    for (int it = 0; it < 2; ++it){
        int idx = it*512 + tid;
        int c = idx >> 4, i4 = idx & 15;
        float4 v = __ldg(reinterpret_cast<const float4*>(P + c*NPTS + qbase) + i4);
        v.x *= -2.f; v.y *= -2.f; v.z *= -2.f; v.w *= -2.f;
        float4* dst = reinterpret_cast<float4*>(Qd + c*128 + i4*8);
        dst[0] = make_float4(v.x, v.x, v.y, v.y);
        dst[1] = make_float4(v.z, v.z, v.w, v.w);
    }
    // load sq-norm cache (1024 float4 -> 2 each)
    #pragma unroll
    for (int it = 0; it < 2; ++it){
        int idx = it*512 + tid;
        reinterpret_cast<float4*>(Ss)[idx] =
            __ldg(reinterpret_cast<const float4*>(g_sq + b*NPTS) + idx);
    }

    // prologue: async-fill chunk 0 into buffer 0
    #pragma unroll
    for (int it = 0; it < 4; ++it){
        int idx = it*512 + tid;
        int c = idx >> 5, i4 = idx & 31;
        cp16(csb + (uint32_t)((c*128 + i4*4)*4), P + c*NPTS + i4*4);
    }
    asm volatile("cp.async.commit_group;");

    // per-(warp,query) sorted list: lane l holds l-th smallest
    float Lv[4]; int Li[4]; float thr[4];
    #pragma unroll
    for (int qi = 0; qi < 4; ++qi){ Lv[qi] = 3.0e38f; Li[qi] = 0; thr[qi] = 3.0e38f; }

    const int q0 = wid * 4;      // this warp's first query
    const int m0 = lane * 4;     // this lane's candidate base within chunk

    #pragma unroll 1
    for (int chunk = 0; chunk < NCHUNK; ++chunk){
        const int mbase = chunk * 128;
        const float* Cb = Cs + (chunk & 1) * (64*128);

        asm volatile("cp.async.wait_group 0;");   // my chunk-k copies landed
        __syncthreads();                          // all copies visible + prev compute done

        // issue prefetch of chunk k+1 into the other buffer (race-free post-sync)
        if (chunk + 1 < NCHUNK){
            const uint32_t dstb = csb + (uint32_t)(((chunk+1) & 1) * 64*128*4);
            const float* src = P + (chunk+1)*128;
            #pragma unroll
            for (int it = 0; it < 4; ++it){
                int idx = it*512 + tid;
                int c = idx >> 5, i4 = idx & 31;
                cp16(dstb + (uint32_t)((c*128 + i4*4)*4), src + c*NPTS + i4*4);
            }
            asm volatile("cp.async.commit_group;");
        }

        // acc init = sq of candidates, loaded directly as adjacent pairs
        ulonglong2 sqp = *reinterpret_cast<const ulonglong2*>(Ss + mbase + m0);
        unsigned long long acc[4][2];
        #pragma unroll
        for (int qi = 0; qi < 4; ++qi){ acc[qi][0] = sqp.x; acc[qi][1] = sqp.y; }

        // GEMM: 4 queries (duplicated-pair operands) x 2 candidate-pairs per lane
        #pragma unroll 4
        for (int c = 0; c < CH; ++c){
            const float* qrow = Qd + c*128 + q0*2;
            ulonglong2 qva = *reinterpret_cast<const ulonglong2*>(qrow);      // (q0,q0),(q1,q1)
            ulonglong2 qvb = *reinterpret_cast<const ulonglong2*>(qrow + 4);  // (q2,q2),(q3,q3)
            ulonglong2 cvp = *reinterpret_cast<const ulonglong2*>(Cb + c*128 + m0);
            acc[0][0] = fma2(qva.x, cvp.x, acc[0][0]);
            acc[0][1] = fma2(qva.x, cvp.y, acc[0][1]);
            acc[1][0] = fma2(qva.y, cvp.x, acc[1][0]);
            acc[1][1] = fma2(qva.y, cvp.y, acc[1][1]);
            acc[2][0] = fma2(qvb.x, cvp.x, acc[2][0]);
            acc[2][1] = fma2(qvb.x, cvp.y, acc[2][1]);
            acc[3][0] = fma2(qvb.y, cvp.x, acc[3][0]);
            acc[3][1] = fma2(qvb.y, cvp.y, acc[3][1]);
        }

        // unpack scores: sc[qi][j] = score of candidate m0+j (ascending m)
        float sc[4][4];
        #pragma unroll
        for (int qi = 0; qi < 4; ++qi){
            float2 d0 = u2f2(acc[qi][0]), d1 = u2f2(acc[qi][1]);
            sc[qi][0] = d0.x; sc[qi][1] = d0.y; sc[qi][2] = d1.x; sc[qi][3] = d1.y;
        }

        // selection with per-query min-prefilter; short insert chains
        #pragma unroll
        for (int qi = 0; qi < 4; ++qi){
            float mn = fminf(fminf(sc[qi][0], sc[qi][1]), fminf(sc[qi][2], sc[qi][3]));
            if (!__any_sync(0xffffffffu, mn < thr[qi])) continue;
            #pragma unroll
            for (int j = 0; j < 4; ++j){
                float sj = sc[qi][j];
                unsigned mask = __ballot_sync(0xffffffffu, sj < thr[qi]);
                while (mask){
                    int src = __ffs(mask) - 1;
                    mask &= mask - 1;
                    float v = __shfl_sync(0xffffffffu, sj, src);
                    int gi = mbase + src*4 + j;
                    int pos = __popc(__ballot_sync(0xffffffffu, Lv[qi] <= v));
                    float upv = __shfl_up_sync(0xffffffffu, Lv[qi], 1);
                    int   upi = __shfl_up_sync(0xffffffffu, Li[qi], 1);
                    if (lane == pos){ Lv[qi] = v; Li[qi] = gi; }
                    else if (lane > pos){ Lv[qi] = upv; Li[qi] = upi; }
                }
                thr[qi] = __shfl_sync(0xffffffffu, Lv[qi], 31);  // once per j
            }
        }
        // no trailing sync: next iteration's wait+sync gates everything
    }

    // write indices: lane l holds l-th nearest of each owned query
    #pragma unroll
    for (int qi = 0; qi < 4; ++qi)
        g_idx[(b*NPTS + qbase + q0 + qi)*KNN + lane] = Li[qi];
}

// ---------------- kernel 2: Y1 = X*(W1-W2)^T, Y2 = X*W2^T ----------------
__global__ void __launch_bounds__(256, 1) ygemm_kernel(const float* __restrict__ points){
    extern __shared__ float smf[];
    float* Xs  = smf;           // [64][128]
    float* W1s = Xs + 64*128;   // [64][64]
    float* W2s = W1s + 64*64;   // [64][64]

    const int tid = threadIdx.x;
    const int b = blockIdx.x >> 5;
    const int nbase = (blockIdx.x & 31) * 128;
    const float* P = points + b*CH*NPTS;

    #pragma unroll
    for (int it = 0; it < 8; ++it){
        int idx = it*256 + tid;
        int c = idx >> 5, i4 = idx & 31;
        reinterpret_cast<float4*>(Xs + c*128)[i4] =
            __ldg(reinterpret_cast<const float4*>(P + c*NPTS + nbase) + i4);
    }
    #pragma unroll
    for (int it = 0; it < 4; ++it){
        int idx = it*256 + tid;
        reinterpret_cast<float4*>(W1s)[idx] = __ldg(reinterpret_cast<const float4*>(g_Wt1) + idx);
        reinterpret_cast<float4*>(W2s)[idx] = __ldg(reinterpret_cast<const float4*>(g_Wt2) + idx);
    }
    __syncthreads();

    const int n0 = (tid & 31) * 4;
    const int o0 = (tid >> 5) * 8;
    float acc1[4][8], acc2[4][8];
    #pragma unroll
    for (int j = 0; j < 4; ++j)
        #pragma unroll
        for (int r = 0; r < 8; ++r){ acc1[j][r] = 0.f; acc2[j][r] = 0.f; }

    #pragma unroll 8
    for (int c = 0; c < CH; ++c){
        float4 a   = *reinterpret_cast<const float4*>(Xs  + c*128 + n0);
        float4 w10 = *reinterpret_cast<const float4*>(W1s + c*64 + o0);
        float4 w11 = *reinterpret_cast<const float4*>(W1s + c*64 + o0 + 4);
        float4 w20 = *reinterpret_cast<const float4*>(W2s + c*64 + o0);
        float4 w21 = *reinterpret_cast<const float4*>(W2s + c*64 + o0 + 4);
        float af[4]  = {a.x, a.y, a.z, a.w};
        float w1f[8] = {w10.x,w10.y,w10.z,w10.w,w11.x,w11.y,w11.z,w11.w};
        float w2f[8] = {w20.x,w20.y,w20.z,w20.w,w21.x,w21.y,w21.z,w21.w};
        #pragma unroll
        for (int j = 0; j < 4; ++j)
            #pragma unroll
            for (int r = 0; r < 8; ++r){
                acc1[j][r] = fmaf(af[j], w1f[r], acc1[j][r]);
                acc2[j][r] = fmaf(af[j], w2f[r], acc2[j][r]);
            }
    }

    #pragma unroll
    for (int j = 0; j < 4; ++j){
        int row = (b*NPTS + nbase + n0 + j)*NOUT + o0;
        *reinterpret_cast<float4*>(g_Y1 + row)     = make_float4(acc1[j][0],acc1[j][1],acc1[j][2],acc1[j][3]);
        *reinterpret_cast<float4*>(g_Y1 + row + 4) = make_float4(acc1[j][4],acc1[j][5],acc1[j][6],acc1[j][7]);
        *reinterpret_cast<float4*>(g_Y2 + row)     = make_float4(acc2[j][0],acc2[j][1],acc2[j][2],acc2[j][3]);
        *reinterpret_cast<float4*>(g_Y2 + row + 4) = make_float4(acc2[j][4],acc2[j][5],acc2[j][6],acc2[j][7]);
    }
}

// ---------------- kernel 3: gather neighbors, h stats, per-(n,o) max/min over k ----------------
__global__ void __launch_bounds__(256, 1) gather_kernel(){
    __shared__ float ssum[NOUT], ssum2[NOUT];
    const int tid = threadIdx.x;
    if (tid < NOUT){ ssum[tid] = 0.f; ssum2[tid] = 0.f; }
    __syncthreads();

    const int b = blockIdx.x >> 6;
    const int nbase = (blockIdx.x & 63) * 64;
    const int lane = tid & 31, wid = tid >> 5;
    const int half = lane >> 4;
    const int c4 = lane & 15;

    const float4* Y1f = reinterpret_cast<const float4*>(g_Y1);
    const float4* Y2f = reinterpret_cast<const float4*>(g_Y2);
    float4* hmaxf = reinterpret_cast<float4*>(g_hmax);
    float4* hminf = reinterpret_cast<float4*>(g_hmin);

    float a0=0.f, a1=0.f, a2=0.f, a3=0.f;
    float b0=0.f, b1=0.f, b2=0.f, b3=0.f;

    #pragma unroll 1
    for (int it = 0; it < 4; ++it){
        int np  = nbase + it*16 + wid*2;
        int bnp = b*NPTS + np;
        int ia = g_idx[ bnp   *KNN + lane];
        int ib = g_idx[(bnp+1)*KNN + lane];
        int bn = bnp + half;
        float4 y1 = __ldg(Y1f + bn*16 + c4);
        float4 mx = make_float4(-3.0e38f,-3.0e38f,-3.0e38f,-3.0e38f);
        float4 mn = make_float4( 3.0e38f, 3.0e38f, 3.0e38f, 3.0e38f);
        #pragma unroll
        for (int k = 0; k < KNN; ++k){
            int ma = __shfl_sync(0xffffffffu, ia, k);
            int mb = __shfl_sync(0xffffffffu, ib, k);
            int m  = half ? mb : ma;
            float4 y2 = __ldg(Y2f + (b*NPTS + m)*16 + c4);
            float h0 = y1.x + y2.x, h1 = y1.y + y2.y, h2 = y1.z + y2.z, h3 = y1.w + y2.w;
            a0 += h0; a1 += h1; a2 += h2; a3 += h3;
            b0 = fmaf(h0,h0,b0); b1 = fmaf(h1,h1,b1); b2 = fmaf(h2,h2,b2); b3 = fmaf(h3,h3,b3);
            mx.x = fmaxf(mx.x,h0); mx.y = fmaxf(mx.y,h1); mx.z = fmaxf(mx.z,h2); mx.w = fmaxf(mx.w,h3);
            mn.x = fminf(mn.x,h0); mn.y = fminf(mn.y,h1); mn.z = fminf(mn.z,h2); mn.w = fminf(mn.w,h3);
        }
        hmaxf[bn*16 + c4] = mx;
        hminf[bn*16 + c4] = mn;
    }

    atomicAdd(&ssum [c4*4+0], a0); atomicAdd(&ssum [c4*4+1], a1);
    atomicAdd(&ssum [c4*4+2], a2); atomicAdd(&ssum [c4*4+3], a3);
    atomicAdd(&ssum2[c4*4+0], b0); atomicAdd(&ssum2[c4*4+1], b1);
    atomicAdd(&ssum2[c4*4+2], b2); atomicAdd(&ssum2[c4*4+3], b3);
    __syncthreads();
    if (tid < NOUT){
        atomicAdd(&g_sum[tid],   ssum[tid]);
        atomicAdd(&g_sumsq[tid], ssum2[tid]);
    }
}

// ---------------- kernel 4: BN scale/shift ----------------
__global__ void finalize_kernel(const float* __restrict__ gamma,
                                const float* __restrict__ beta){
    int o = threadIdx.x;
    if (o < NOUT){
        const float inv = 1.f / (float)(BATCH*NPTS*KNN);
        float mean = g_sum[o] * inv;
        float var  = g_sumsq[o] * inv - mean*mean;
        float a = gamma[o] * rsqrtf(var + 1e-5f);
        g_a[o] = a;
        g_c[o] = beta[o] - a*mean;
    }
}

// ---------------- kernel 5: affine + relu + transpose to (B,O,N) ----------------
__global__ void __launch_bounds__(256, 1) output_kernel(float* __restrict__ out){
    __shared__ float smx[64][65];
    __shared__ float smn[64][65];
    const int tid = threadIdx.x;
    const int b = blockIdx.x >> 6;
    const int nbase = (blockIdx.x & 63) * 64;
    const float4* hmaxf = reinterpret_cast<const float4*>(g_hmax);
    const float4* hminf = reinterpret_cast<const float4*>(g_hmin);

    #pragma unroll
    for (int it = 0; it < 4; ++it){
        int idx = it*256 + tid;
        int r = idx >> 4, cc = idx & 15;
        float4 v = __ldg(hmaxf + (b*NPTS + nbase + r)*16 + cc);
        smx[r][cc*4+0] = v.x; smx[r][cc*4+1] = v.y; smx[r][cc*4+2] = v.z; smx[r][cc*4+3] = v.w;
        float4 w = __ldg(hminf + (b*NPTS + nbase + r)*16 + cc);
        smn[r][cc*4+0] = w.x; smn[r][cc*4+1] = w.y; smn[r][cc*4+2] = w.z; smn[r][cc*4+3] = w.w;
    }
    __syncthreads();

    #pragma unroll
    for (int it = 0; it < 16; ++it){
        int o  = it*4 + (tid >> 6);
        int nn = tid & 63;
        float a = g_a[o], c = g_c[o];
        float h = (a >= 0.f) ? smx[nn][o] : smn[nn][o];
        out[b*NOUT*NPTS + o*NPTS + nbase + nn] = fmaxf(fmaf(a, h, c), 0.f);
    }
}

// ---------------- launch ----------------
extern "C" void kernel_launch(void* const* d_in, const int* in_sizes, int n_in,
                              void* d_out, int out_size){
    const float* points = (const float*)d_in[0];   // (B, C, N)
    const float* W      = (const float*)d_in[1];   // (O, 2C)
    const float* gamma  = (const float*)d_in[2];   // (O,)
    const float* beta   = (const float*)d_in[3];   // (O,)
    float* out = (float*)d_out;                    // (B, O, N)

    const int KNN_SMEM = (64*128 + 2*64*128 + 4096) * 4;   // 114688 B
    cudaFuncSetAttribute((const void*)knn_kernel,
                         cudaFuncAttributeMaxDynamicSharedMemorySize, KNN_SMEM);
    cudaFuncSetAttribute((const void*)ygemm_kernel,
                         cudaFuncAttributeMaxDynamicSharedMemorySize, 64*1024);

    wprep_kernel   <<<16, 256>>>(W);
    sqnorm_kernel  <<<64, 256>>>(points);
    zero_kernel    <<<1, 64>>>();
    knn_kernel     <<<BATCH*(NPTS/64), 512, KNN_SMEM>>>(points);
    ygemm_kernel   <<<BATCH*(NPTS/128), 256, 64*1024>>>(points);
    gather_kernel  <<<BATCH*(NPTS/64), 256>>>();
    finalize_kernel<<<1, 64>>>(gamma, beta);
    output_kernel  <<<BATCH*(NPTS/64), 256>>>(out);
}

// round 17
// speedup vs baseline: 1.1649x; 1.1632x over previous
#include <cuda_runtime.h>
#include <cstdint>

#define BATCH 4
#define CH    64
#define NPTS  4096
#define KNN   32
#define NOUT  64
#define NCHUNK (NPTS/128)

// ---------------- device scratch (static: no allocations allowed) ----------------
__device__ float g_sq   [BATCH*NPTS];
__device__ int   g_idx  [BATCH*NPTS*KNN];
__device__ float g_Y1   [BATCH*NPTS*NOUT];
__device__ float g_Y2   [BATCH*NPTS*NOUT];
__device__ float g_hmax [BATCH*NPTS*NOUT];
__device__ float g_hmin [BATCH*NPTS*NOUT];
__device__ float g_Wt1  [CH*NOUT];
__device__ float g_Wt2  [CH*NOUT];
__device__ float g_sum  [NOUT];
__device__ float g_sumsq[NOUT];
__device__ float g_a    [NOUT];
__device__ float g_c    [NOUT];

// ---------------- packed fp32x2 helpers (Blackwell FFMA2) ----------------
__device__ __forceinline__ unsigned long long pack2(float x){
    unsigned long long d; unsigned int xi = __float_as_uint(x);
    asm("mov.b64 %0, {%1, %1};" : "=l"(d) : "r"(xi));
    return d;
}
__device__ __forceinline__ unsigned long long fma2(unsigned long long a,
                                                   unsigned long long b,
                                                   unsigned long long c){
    unsigned long long d;
    asm("fma.rn.f32x2 %0, %1, %2, %3;" : "=l"(d) : "l"(a), "l"(b), "l"(c));
    return d;
}
__device__ __forceinline__ float2 u2f2(unsigned long long u){
    float2 f;
    asm("mov.b64 {%0, %1}, %2;" : "=f"(f.x), "=f"(f.y) : "l"(u));
    return f;
}
__device__ __forceinline__ uint32_t smem_u32(const void* p){
    uint32_t a;
    asm("{ .reg .u64 t; cvta.to.shared.u64 t, %1; cvt.u32.u64 %0, t; }" : "=r"(a) : "l"(p));
    return a;
}
__device__ __forceinline__ void cp16(uint32_t dst, const void* src){
    asm volatile("cp.async.ca.shared.global [%0], [%1], 16;" :: "r"(dst), "l"(src));
}

// ---------------- kernel 0a: Wt1 = (W1-W2)^T, Wt2 = W2^T + zero BN accumulators ----------------
__global__ void wprep_kernel(const float* __restrict__ W){
    int t = blockIdx.x*256 + threadIdx.x;
    if (t < CH*NOUT){
        int o = t & 63, c = t >> 6;
        float w1 = W[o*2*CH + c];
        float w2 = W[o*2*CH + CH + c];
        g_Wt1[c*NOUT + o] = w1 - w2;
        g_Wt2[c*NOUT + o] = w2;
    }
    if (blockIdx.x == 0 && t < NOUT){ g_sum[t] = 0.f; g_sumsq[t] = 0.f; }
}

// ---------------- kernel 0b: squared norms ----------------
__global__ void sqnorm_kernel(const float* __restrict__ points){
    int t = blockIdx.x*256 + threadIdx.x;         // 0..16383
    int b = t >> 12, n = t & (NPTS-1);
    const float* P = points + b*CH*NPTS + n;
    float s = 0.f;
    #pragma unroll
    for (int c = 0; c < CH; ++c){ float v = __ldg(P + c*NPTS); s = fmaf(v, v, s); }
    g_sq[t] = s;
}

// ---------------- kernel 1: fused distance GEMM + register top-32 ----------------
// grid = BATCH*64 blocks x 512 threads (16 warps), 2 blocks/SM (64 regs).
// Block owns 64 queries; warp w owns queries [4w, 4w+4). Streams 4096
// candidates in chunks of 128, double-buffered via cp.async with ONE
// __syncthreads per chunk (wait -> sync -> prefetch(k+1) -> compute(k)).
// Qs pre-scaled by -2; acc init = sq_m, so score = sq_m - 2*dot directly.
// Selection = short-chain sorted-list inserts (thr updated once per j).
// smem: Qs[64][64] 16K + Cs 2x[64][128] 64K + Ss[4096] 16K = 96KB.
__global__ void __launch_bounds__(512, 2) knn_kernel(const float* __restrict__ points){
    extern __shared__ float sm[];
    float* Qs = sm;               // [64][64]  (scaled by -2)
    float* Cs = Qs + 64*64;       // 2 x [64][128] (raw candidates)
    float* Ss = Cs + 2*64*128;    // [4096] candidate sq-norms
    const uint32_t csb = smem_u32(Cs);

    const int tid  = threadIdx.x;
    const int lane = tid & 31;
    const int wid  = tid >> 5;
    const int b     = blockIdx.x >> 6;
    const int qbase = (blockIdx.x & 63) * 64;
    const float* P = points + b*CH*NPTS;

    // load query tile Qs[c][i], scaled by -2  (1024 float4 -> 2 each)
    #pragma unroll
    for (int it = 0; it < 2; ++it){
        int idx = it*512 + tid;
        int c = idx >> 4, i4 = idx & 15;
        float4 v = __ldg(reinterpret_cast<const float4*>(P + c*NPTS + qbase) + i4);
        v.x *= -2.f; v.y *= -2.f; v.z *= -2.f; v.w *= -2.f;
        reinterpret_cast<float4*>(Qs + c*64)[i4] = v;
    }
    // load sq-norm cache (1024 float4 -> 2 each)
    #pragma unroll
    for (int it = 0; it < 2; ++it){
        int idx = it*512 + tid;
        reinterpret_cast<float4*>(Ss)[idx] =
            __ldg(reinterpret_cast<const float4*>(g_sq + b*NPTS) + idx);
    }

    // prologue: async-fill chunk 0 into buffer 0
    #pragma unroll
    for (int it = 0; it < 4; ++it){
        int idx = it*512 + tid;
        int c = idx >> 5, i4 = idx & 31;
        cp16(csb + (uint32_t)((c*128 + i4*4)*4), P + c*NPTS + i4*4);
    }
    asm volatile("cp.async.commit_group;");

    // per-(warp,query) sorted list: lane l holds l-th smallest
    float Lv[4]; int Li[4]; float thr[4];
    #pragma unroll
    for (int qi = 0; qi < 4; ++qi){ Lv[qi] = 3.0e38f; Li[qi] = 0; thr[qi] = 3.0e38f; }

    const int q0 = wid * 4;      // this warp's first query (broadcast smem reads)
    const int m0 = lane * 4;     // this lane's candidate base within chunk

    #pragma unroll 1
    for (int chunk = 0; chunk < NCHUNK; ++chunk){
        const int mbase = chunk * 128;
        const float* Cb = Cs + (chunk & 1) * (64*128);

        asm volatile("cp.async.wait_group 0;");   // my chunk-k copies landed
        __syncthreads();                          // all copies visible + prev compute done

        // issue prefetch of chunk k+1 into the other buffer (race-free post-sync)
        if (chunk + 1 < NCHUNK){
            const uint32_t dstb = csb + (uint32_t)(((chunk+1) & 1) * 64*128*4);
            const float* src = P + (chunk+1)*128;
            #pragma unroll
            for (int it = 0; it < 4; ++it){
                int idx = it*512 + tid;
                int c = idx >> 5, i4 = idx & 31;
                cp16(dstb + (uint32_t)((c*128 + i4*4)*4), src + c*NPTS + i4*4);
            }
            asm volatile("cp.async.commit_group;");
        }

        // acc init = sq of candidates
        float4 sqv = *reinterpret_cast<const float4*>(Ss + mbase + m0);
        unsigned long long acc[2][4];
        acc[0][0] = acc[1][0] = pack2(sqv.x);
        acc[0][1] = acc[1][1] = pack2(sqv.y);
        acc[0][2] = acc[1][2] = pack2(sqv.z);
        acc[0][3] = acc[1][3] = pack2(sqv.w);

        // GEMM: 4 queries (2 f32x2 pairs, pre-scaled by -2) x 4 candidates per lane
        #pragma unroll 8
        for (int c = 0; c < CH; ++c){
            ulonglong2 qv = *reinterpret_cast<const ulonglong2*>(Qs + c*64 + q0); // bcast
            float4 cv = *reinterpret_cast<const float4*>(Cb + c*128 + m0);
            unsigned long long bp0 = pack2(cv.x), bp1 = pack2(cv.y),
                               bp2 = pack2(cv.z), bp3 = pack2(cv.w);
            acc[0][0] = fma2(qv.x, bp0, acc[0][0]);
            acc[0][1] = fma2(qv.x, bp1, acc[0][1]);
            acc[0][2] = fma2(qv.x, bp2, acc[0][2]);
            acc[0][3] = fma2(qv.x, bp3, acc[0][3]);
            acc[1][0] = fma2(qv.y, bp0, acc[1][0]);
            acc[1][1] = fma2(qv.y, bp1, acc[1][1]);
            acc[1][2] = fma2(qv.y, bp2, acc[1][2]);
            acc[1][3] = fma2(qv.y, bp3, acc[1][3]);
        }

        // unpack scores: sc[qi][j]
        float sc[4][4];
        #pragma unroll
        for (int p = 0; p < 2; ++p){
            float2 d0 = u2f2(acc[p][0]), d1 = u2f2(acc[p][1]);
            float2 d2 = u2f2(acc[p][2]), d3 = u2f2(acc[p][3]);
            sc[2*p  ][0] = d0.x; sc[2*p  ][1] = d1.x; sc[2*p  ][2] = d2.x; sc[2*p  ][3] = d3.x;
            sc[2*p+1][0] = d0.y; sc[2*p+1][1] = d1.y; sc[2*p+1][2] = d2.y; sc[2*p+1][3] = d3.y;
        }

        // selection with per-query min-prefilter; short insert chains
        #pragma unroll
        for (int qi = 0; qi < 4; ++qi){
            float mn = fminf(fminf(sc[qi][0], sc[qi][1]), fminf(sc[qi][2], sc[qi][3]));
            if (!__any_sync(0xffffffffu, mn < thr[qi])) continue;
            #pragma unroll
            for (int j = 0; j < 4; ++j){
                float sj = sc[qi][j];
                unsigned mask = __ballot_sync(0xffffffffu, sj < thr[qi]);
                while (mask){
                    int src = __ffs(mask) - 1;
                    mask &= mask - 1;
                    float v = __shfl_sync(0xffffffffu, sj, src);
                    int gi = mbase + src*4 + j;
                    int pos = __popc(__ballot_sync(0xffffffffu, Lv[qi] <= v));
                    float upv = __shfl_up_sync(0xffffffffu, Lv[qi], 1);
                    int   upi = __shfl_up_sync(0xffffffffu, Li[qi], 1);
                    if (lane == pos){ Lv[qi] = v; Li[qi] = gi; }
                    else if (lane > pos){ Lv[qi] = upv; Li[qi] = upi; }
                }
                thr[qi] = __shfl_sync(0xffffffffu, Lv[qi], 31);  // once per j
            }
        }
        // no trailing sync: next iteration's wait+sync gates everything
    }

    // write indices: lane l holds l-th nearest of each owned query
    #pragma unroll
    for (int qi = 0; qi < 4; ++qi)
        g_idx[(b*NPTS + qbase + q0 + qi)*KNN + lane] = Li[qi];
}

// ---------------- kernel 2: Y1 = X*(W1-W2)^T, Y2 = X*W2^T ----------------
__global__ void __launch_bounds__(256, 1) ygemm_kernel(const float* __restrict__ points){
    extern __shared__ float smf[];
    float* Xs  = smf;           // [64][128]
    float* W1s = Xs + 64*128;   // [64][64]
    float* W2s = W1s + 64*64;   // [64][64]

    const int tid = threadIdx.x;
    const int b = blockIdx.x >> 5;
    const int nbase = (blockIdx.x & 31) * 128;
    const float* P = points + b*CH*NPTS;

    #pragma unroll
    for (int it = 0; it < 8; ++it){
        int idx = it*256 + tid;
        int c = idx >> 5, i4 = idx & 31;
        reinterpret_cast<float4*>(Xs + c*128)[i4] =
            __ldg(reinterpret_cast<const float4*>(P + c*NPTS + nbase) + i4);
    }
    #pragma unroll
    for (int it = 0; it < 4; ++it){
        int idx = it*256 + tid;
        reinterpret_cast<float4*>(W1s)[idx] = __ldg(reinterpret_cast<const float4*>(g_Wt1) + idx);
        reinterpret_cast<float4*>(W2s)[idx] = __ldg(reinterpret_cast<const float4*>(g_Wt2) + idx);
    }
    __syncthreads();

    const int n0 = (tid & 31) * 4;
    const int o0 = (tid >> 5) * 8;
    float acc1[4][8], acc2[4][8];
    #pragma unroll
    for (int j = 0; j < 4; ++j)
        #pragma unroll
        for (int r = 0; r < 8; ++r){ acc1[j][r] = 0.f; acc2[j][r] = 0.f; }

    #pragma unroll 8
    for (int c = 0; c < CH; ++c){
        float4 a   = *reinterpret_cast<const float4*>(Xs  + c*128 + n0);
        float4 w10 = *reinterpret_cast<const float4*>(W1s + c*64 + o0);
        float4 w11 = *reinterpret_cast<const float4*>(W1s + c*64 + o0 + 4);
        float4 w20 = *reinterpret_cast<const float4*>(W2s + c*64 + o0);
        float4 w21 = *reinterpret_cast<const float4*>(W2s + c*64 + o0 + 4);
        float af[4]  = {a.x, a.y, a.z, a.w};
        float w1f[8] = {w10.x,w10.y,w10.z,w10.w,w11.x,w11.y,w11.z,w11.w};
        float w2f[8] = {w20.x,w20.y,w20.z,w20.w,w21.x,w21.y,w21.z,w21.w};
        #pragma unroll
        for (int j = 0; j < 4; ++j)
            #pragma unroll
            for (int r = 0; r < 8; ++r){
                acc1[j][r] = fmaf(af[j], w1f[r], acc1[j][r]);
                acc2[j][r] = fmaf(af[j], w2f[r], acc2[j][r]);
            }
    }

    #pragma unroll
    for (int j = 0; j < 4; ++j){
        int row = (b*NPTS + nbase + n0 + j)*NOUT + o0;
        *reinterpret_cast<float4*>(g_Y1 + row)     = make_float4(acc1[j][0],acc1[j][1],acc1[j][2],acc1[j][3]);
        *reinterpret_cast<float4*>(g_Y1 + row + 4) = make_float4(acc1[j][4],acc1[j][5],acc1[j][6],acc1[j][7]);
        *reinterpret_cast<float4*>(g_Y2 + row)     = make_float4(acc2[j][0],acc2[j][1],acc2[j][2],acc2[j][3]);
        *reinterpret_cast<float4*>(g_Y2 + row + 4) = make_float4(acc2[j][4],acc2[j][5],acc2[j][6],acc2[j][7]);
    }
}

// ---------------- kernel 3: gather neighbors, h stats, per-(n,o) max/min over k ----------------
__global__ void __launch_bounds__(256, 1) gather_kernel(){
    __shared__ float ssum[NOUT], ssum2[NOUT];
    const int tid = threadIdx.x;
    if (tid < NOUT){ ssum[tid] = 0.f; ssum2[tid] = 0.f; }
    __syncthreads();

    const int b = blockIdx.x >> 6;
    const int nbase = (blockIdx.x & 63) * 64;
    const int lane = tid & 31, wid = tid >> 5;
    const int half = lane >> 4;
    const int c4 = lane & 15;

    const float4* Y1f = reinterpret_cast<const float4*>(g_Y1);
    const float4* Y2f = reinterpret_cast<const float4*>(g_Y2);
    float4* hmaxf = reinterpret_cast<float4*>(g_hmax);
    float4* hminf = reinterpret_cast<float4*>(g_hmin);

    float a0=0.f, a1=0.f, a2=0.f, a3=0.f;
    float b0=0.f, b1=0.f, b2=0.f, b3=0.f;

    #pragma unroll 1
    for (int it = 0; it < 4; ++it){
        int np  = nbase + it*16 + wid*2;
        int bnp = b*NPTS + np;
        int ia = g_idx[ bnp   *KNN + lane];
        int ib = g_idx[(bnp+1)*KNN + lane];
        int bn = bnp + half;
        float4 y1 = __ldg(Y1f + bn*16 + c4);
        float4 mx = make_float4(-3.0e38f,-3.0e38f,-3.0e38f,-3.0e38f);
        float4 mn = make_float4( 3.0e38f, 3.0e38f, 3.0e38f, 3.0e38f);
        #pragma unroll
        for (int k = 0; k < KNN; ++k){
            int ma = __shfl_sync(0xffffffffu, ia, k);
            int mb = __shfl_sync(0xffffffffu, ib, k);
            int m  = half ? mb : ma;
            float4 y2 = __ldg(Y2f + (b*NPTS + m)*16 + c4);
            float h0 = y1.x + y2.x, h1 = y1.y + y2.y, h2 = y1.z + y2.z, h3 = y1.w + y2.w;
            a0 += h0; a1 += h1; a2 += h2; a3 += h3;
            b0 = fmaf(h0,h0,b0); b1 = fmaf(h1,h1,b1); b2 = fmaf(h2,h2,b2); b3 = fmaf(h3,h3,b3);
            mx.x = fmaxf(mx.x,h0); mx.y = fmaxf(mx.y,h1); mx.z = fmaxf(mx.z,h2); mx.w = fmaxf(mx.w,h3);
            mn.x = fminf(mn.x,h0); mn.y = fminf(mn.y,h1); mn.z = fminf(mn.z,h2); mn.w = fminf(mn.w,h3);
        }
        hmaxf[bn*16 + c4] = mx;
        hminf[bn*16 + c4] = mn;
    }

    atomicAdd(&ssum [c4*4+0], a0); atomicAdd(&ssum [c4*4+1], a1);
    atomicAdd(&ssum [c4*4+2], a2); atomicAdd(&ssum [c4*4+3], a3);
    atomicAdd(&ssum2[c4*4+0], b0); atomicAdd(&ssum2[c4*4+1], b1);
    atomicAdd(&ssum2[c4*4+2], b2); atomicAdd(&ssum2[c4*4+3], b3);
    __syncthreads();
    if (tid < NOUT){
        atomicAdd(&g_sum[tid],   ssum[tid]);
        atomicAdd(&g_sumsq[tid], ssum2[tid]);
    }
}

// ---------------- kernel 4: BN scale/shift ----------------
__global__ void finalize_kernel(const float* __restrict__ gamma,
                                const float* __restrict__ beta){
    int o = threadIdx.x;
    if (o < NOUT){
        const float inv = 1.f / (float)(BATCH*NPTS*KNN);
        float mean = g_sum[o] * inv;
        float var  = g_sumsq[o] * inv - mean*mean;
        float a = gamma[o] * rsqrtf(var + 1e-5f);
        g_a[o] = a;
        g_c[o] = beta[o] - a*mean;
    }
}

// ---------------- kernel 5: affine + relu + transpose to (B,O,N) ----------------
__global__ void __launch_bounds__(256, 1) output_kernel(float* __restrict__ out){
    __shared__ float smx[64][65];
    __shared__ float smn[64][65];
    const int tid = threadIdx.x;
    const int b = blockIdx.x >> 6;
    const int nbase = (blockIdx.x & 63) * 64;
    const float4* hmaxf = reinterpret_cast<const float4*>(g_hmax);
    const float4* hminf = reinterpret_cast<const float4*>(g_hmin);

    #pragma unroll
    for (int it = 0; it < 4; ++it){
        int idx = it*256 + tid;
        int r = idx >> 4, cc = idx & 15;
        float4 v = __ldg(hmaxf + (b*NPTS + nbase + r)*16 + cc);
        smx[r][cc*4+0] = v.x; smx[r][cc*4+1] = v.y; smx[r][cc*4+2] = v.z; smx[r][cc*4+3] = v.w;
        float4 w = __ldg(hminf + (b*NPTS + nbase + r)*16 + cc);
        smn[r][cc*4+0] = w.x; smn[r][cc*4+1] = w.y; smn[r][cc*4+2] = w.z; smn[r][cc*4+3] = w.w;
    }
    __syncthreads();

    #pragma unroll
    for (int it = 0; it < 16; ++it){
        int o  = it*4 + (tid >> 6);
        int nn = tid & 63;
        float a = g_a[o], c = g_c[o];
        float h = (a >= 0.f) ? smx[nn][o] : smn[nn][o];
        out[b*NOUT*NPTS + o*NPTS + nbase + nn] = fmaxf(fmaf(a, h, c), 0.f);
    }
}

// ---------------- launch ----------------
extern "C" void kernel_launch(void* const* d_in, const int* in_sizes, int n_in,
                              void* d_out, int out_size){
    const float* points = (const float*)d_in[0];   // (B, C, N)
    const float* W      = (const float*)d_in[1];   // (O, 2C)
    const float* gamma  = (const float*)d_in[2];   // (O,)
    const float* beta   = (const float*)d_in[3];   // (O,)
    float* out = (float*)d_out;                    // (B, O, N)

    const int KNN_SMEM = (64*64 + 2*64*128 + 4096) * 4;   // 98304 B
    cudaFuncSetAttribute((const void*)knn_kernel,
                         cudaFuncAttributeMaxDynamicSharedMemorySize, KNN_SMEM);
    cudaFuncSetAttribute((const void*)ygemm_kernel,
                         cudaFuncAttributeMaxDynamicSharedMemorySize, 64*1024);

    wprep_kernel   <<<16, 256>>>(W);
    sqnorm_kernel  <<<64, 256>>>(points);
    knn_kernel     <<<BATCH*(NPTS/64), 512, KNN_SMEM>>>(points);
    ygemm_kernel   <<<BATCH*(NPTS/128), 256, 64*1024>>>(points);
    gather_kernel  <<<BATCH*(NPTS/64), 256>>>();
    finalize_kernel<<<1, 64>>>(gamma, beta);
    output_kernel  <<<BATCH*(NPTS/64), 256>>>(out);
}